// round 1
// baseline (speedup 1.0000x reference)
#include <cuda_runtime.h>

#define NN 100000
#define NB 32      // n (bases)
#define MM 16      // m (clusters)
#define KK 32      // k (neighbours)

// ---- device scratch (no allocations allowed) ----
__device__ float g_encoded[NB];
__device__ float g_S[NB * KK];          // S[i][kk]
__device__ __align__(16) float g_a[MM * NB];   // a[c][i] = 1/(w*MU)^2
__device__ __align__(16) float g_E[KK * NB];   // E[kk][i] = encoded[i]/S[i][kk]
__device__ __align__(16) float g_decT[(size_t)NN * NB];  // decoder transposed [N][32]

// ---- k0: init encoded with bias, zero S ----
__global__ void k_zero(const float* __restrict__ encB) {
    int t = blockIdx.x * blockDim.x + threadIdx.x;
    if (t < NB) g_encoded[t] = encB[t];
    if (t < NB * KK) g_S[t] = 0.f;
}

// ---- k1: encoded[i] = b[i] + sum_p x[p]*W[i,p] ----
__global__ void k_encode(const float* __restrict__ x, const float* __restrict__ W) {
    int i = blockIdx.y;
    const float* Wr = W + (size_t)i * NN;
    float acc = 0.f;
    for (int p = blockIdx.x * blockDim.x + threadIdx.x; p < NN;
         p += gridDim.x * blockDim.x)
        acc = fmaf(x[p], Wr[p], acc);
    #pragma unroll
    for (int o = 16; o; o >>= 1) acc += __shfl_xor_sync(0xffffffffu, acc, o);
    __shared__ float s[8];
    int w = threadIdx.x >> 5;
    if ((threadIdx.x & 31) == 0) s[w] = acc;
    __syncthreads();
    if (threadIdx.x == 0) {
        float t = 0.f;
        #pragma unroll
        for (int j = 0; j < 8; j++) t += s[j];
        atomicAdd(&g_encoded[i], t);
    }
}

// ---- k2: bandwidth -> a[c][i] (one block, 512 threads) ----
__global__ void k_bw(const float* __restrict__ bwW, const float* __restrict__ bwB) {
    __shared__ float enc[NB];
    if (threadIdx.x < NB) enc[threadIdx.x] = g_encoded[threadIdx.x];
    __syncthreads();
    int j = threadIdx.x;           // j = i*m + c, j in [0,512)
    float z = bwB[j];
    #pragma unroll
    for (int i = 0; i < NB; i++) z = fmaf(enc[i], bwW[j * NB + i], z);
    float s = 1.f / (1.f + expf(-z));
    float t = s * (100.0f / 60.0f);       // w*MU = sigmoid/60 * 100
    float a = 1.f / (t * t);
    int i = j >> 4, c = j & 15;
    g_a[c * NB + i] = a;
}

// ---- k3: S[i][kk] = sum_p relu(1 - d^2 * a[i, label[p]]) ----
__global__ void k_sumS(const float* __restrict__ nd, const int* __restrict__ lab) {
    __shared__ __align__(16) float sa[MM * NB];
    __shared__ float bS[NB * KK];
    for (int t = threadIdx.x; t < MM * NB; t += blockDim.x) sa[t] = g_a[t];
    for (int t = threadIdx.x; t < NB * KK; t += blockDim.x) bS[t] = 0.f;
    __syncthreads();

    int lane = threadIdx.x & 31;                 // lane == kk
    int warp = (blockIdx.x * blockDim.x + threadIdx.x) >> 5;
    int nwarp = (gridDim.x * blockDim.x) >> 5;

    float acc[NB];
    #pragma unroll
    for (int i = 0; i < NB; i++) acc[i] = 0.f;

    for (int p = warp; p < NN; p += nwarp) {
        float d = nd[p * KK + lane];
        int c = lab[p];
        float md2 = -d * d;
        const float4* ac4 = (const float4*)&sa[c * NB];
        #pragma unroll
        for (int i8 = 0; i8 < 8; i8++) {
            float4 a4 = ac4[i8];
            acc[i8 * 4 + 0] += fmaxf(fmaf(md2, a4.x, 1.f), 0.f);
            acc[i8 * 4 + 1] += fmaxf(fmaf(md2, a4.y, 1.f), 0.f);
            acc[i8 * 4 + 2] += fmaxf(fmaf(md2, a4.z, 1.f), 0.f);
            acc[i8 * 4 + 3] += fmaxf(fmaf(md2, a4.w, 1.f), 0.f);
        }
    }
    #pragma unroll
    for (int i = 0; i < NB; i++)
        atomicAdd(&bS[i * KK + lane], acc[i]);
    __syncthreads();
    for (int t = threadIdx.x; t < NB * KK; t += blockDim.x)
        atomicAdd(&g_S[t], bS[t]);
}

// ---- k4: E[kk][i] = encoded[i]/S[i][kk] (one block, 1024 threads) ----
__global__ void k_E() {
    int t = threadIdx.x;
    int i = t >> 5, kk = t & 31;
    g_E[kk * NB + i] = g_encoded[i] / g_S[i * KK + kk];
}

// ---- k5: transpose decoder [32, N] -> decT [N, 32] ----
__global__ void k_transpose(const float* __restrict__ dec) {
    __shared__ float tile[32][33];
    int p0 = blockIdx.x * 32;
    int tx = threadIdx.x, ty = threadIdx.y;   // (32, 8)
    #pragma unroll
    for (int r = 0; r < 4; r++) {
        int i = ty + 8 * r;
        tile[i][tx] = dec[(size_t)i * NN + p0 + tx];
    }
    __syncthreads();
    #pragma unroll
    for (int r = 0; r < 4; r++) {
        int row = ty + 8 * r;
        g_decT[(size_t)(p0 + row) * NB + tx] = tile[tx][row];
    }
}

// ---- k6: out[p] = sum_kk sum_i E[i,kk]*relu(1-d^2*a[i,c])*decT[nid][i] ----
// warp per p; lane = kk for the coalesced d/nid row loads; then each round
// 4 kk x 8 lanes, each lane covering 4 i-values via one LDG.128 of decT.
__global__ void k_out(const float* __restrict__ nd, const int* __restrict__ nid,
                      const int* __restrict__ lab, float* __restrict__ out) {
    __shared__ __align__(16) float sa[MM * NB];
    __shared__ __align__(16) float sE[KK * NB];
    for (int t = threadIdx.x; t < MM * NB; t += blockDim.x) sa[t] = g_a[t];
    for (int t = threadIdx.x; t < KK * NB; t += blockDim.x) sE[t] = g_E[t];
    __syncthreads();

    int lane = threadIdx.x & 31;
    int warp = (blockIdx.x * blockDim.x + threadIdx.x) >> 5;
    int nwarp = (gridDim.x * blockDim.x) >> 5;
    int r = lane & 7;        // i-chunk index (4 floats = 16B of the 128B row)
    int g = lane >> 3;       // kk subgroup within a round

    for (int p = warp; p < NN; p += nwarp) {
        float d_r = nd[p * KK + lane];
        int q_r = nid[p * KK + lane];
        int c = lab[p];
        float4 av = *(const float4*)&sa[c * NB + r * 4];
        float acc = 0.f;
        #pragma unroll
        for (int t = 0; t < 8; t++) {
            int kk = t * 4 + g;
            float d = __shfl_sync(0xffffffffu, d_r, kk);
            int q = __shfl_sync(0xffffffffu, q_r, kk);
            float md2 = -d * d;
            float4 dv = *(const float4*)&g_decT[(size_t)q * NB + r * 4];
            float4 Ev = *(const float4*)&sE[kk * NB + r * 4];
            float w0 = fmaxf(fmaf(md2, av.x, 1.f), 0.f);
            float w1 = fmaxf(fmaf(md2, av.y, 1.f), 0.f);
            float w2 = fmaxf(fmaf(md2, av.z, 1.f), 0.f);
            float w3 = fmaxf(fmaf(md2, av.w, 1.f), 0.f);
            acc = fmaf(w0 * Ev.x, dv.x, acc);
            acc = fmaf(w1 * Ev.y, dv.y, acc);
            acc = fmaf(w2 * Ev.z, dv.z, acc);
            acc = fmaf(w3 * Ev.w, dv.w, acc);
        }
        #pragma unroll
        for (int o = 16; o; o >>= 1) acc += __shfl_xor_sync(0xffffffffu, acc, o);
        if (lane == 0) out[p] = acc;
    }
}

extern "C" void kernel_launch(void* const* d_in, const int* in_sizes, int n_in,
                              void* d_out, int out_size) {
    const float* x    = (const float*)d_in[0];
    const float* encW = (const float*)d_in[1];
    const float* encB = (const float*)d_in[2];
    const float* dec  = (const float*)d_in[3];
    const float* bwW  = (const float*)d_in[4];
    const float* bwB  = (const float*)d_in[5];
    const float* nd   = (const float*)d_in[6];
    const int*   nidp = (const int*)d_in[7];
    const int*   lab  = (const int*)d_in[8];
    float* out = (float*)d_out;

    k_zero<<<1, 1024>>>(encB);
    k_transpose<<<NN / 32, dim3(32, 8)>>>(dec);        // independent of the rest
    k_encode<<<dim3(10, NB), 256>>>(x, encW);
    k_bw<<<1, MM * NB>>>(bwW, bwB);
    k_sumS<<<296, 256>>>(nd, lab);
    k_E<<<1, NB * KK>>>();
    k_out<<<592, 256>>>(nd, nidp, lab, out);
}

// round 2
// speedup vs baseline: 1.0524x; 1.0524x over previous
#include <cuda_runtime.h>
#include <cuda_fp16.h>

#define NN 100000
#define NB 32      // n (bases)
#define MM 16      // m (clusters)
#define KK 32      // k (neighbours)

// ---- device scratch (no allocations allowed) ----
__device__ float g_encPart[4 * NB];     // encoder partial sums [chunk][i]
__device__ float g_encoded[NB];
__device__ float g_S[NB * KK];          // S[i][kk]
__device__ __align__(16) float g_a[MM * NB];          // a[c][i] = 1/(w*MU)^2
__device__ __align__(128) __half g_decTh[(size_t)NN * NB];  // decoder^T, fp16 [N][32]

// ---- transpose+convert decoder [32, N] -> decTh [N, 32] fp16 ----
__global__ void k_transpose(const float* __restrict__ dec) {
    __shared__ float tile[32][33];
    int p0 = blockIdx.x * 32;
    int tx = threadIdx.x, ty = threadIdx.y;   // (32, 8)
    #pragma unroll
    for (int r = 0; r < 4; r++) {
        int i = ty + 8 * r;
        tile[i][tx] = dec[(size_t)i * NN + p0 + tx];
    }
    __syncthreads();
    #pragma unroll
    for (int r = 0; r < 4; r++) {
        int row = ty + 8 * r;
        g_decTh[(size_t)(p0 + row) * NB + tx] = __float2half(tile[tx][row]);
    }
}

// ---- encoder partials: g_encPart[ck][i] = sum over chunk ck of x[p]*W[i,p] ----
__global__ void k_encode(const float* __restrict__ x, const float* __restrict__ W) {
    int i = blockIdx.y, ck = blockIdx.x;
    const float* Wr = W + (size_t)i * NN;
    int p0 = ck * (NN / 4);
    float acc = 0.f;
    for (int p = p0 + threadIdx.x; p < p0 + NN / 4; p += 256)
        acc = fmaf(x[p], Wr[p], acc);
    #pragma unroll
    for (int o = 16; o; o >>= 1) acc += __shfl_xor_sync(0xffffffffu, acc, o);
    __shared__ float s[8];
    if ((threadIdx.x & 31) == 0) s[threadIdx.x >> 5] = acc;
    __syncthreads();
    if (threadIdx.x == 0) {
        float t = 0.f;
        #pragma unroll
        for (int j = 0; j < 8; j++) t += s[j];
        g_encPart[ck * NB + i] = t;
    }
}

// ---- bandwidth: finalize encoded, zero S, warp-per-j bw linear -> g_a ----
// grid 16 blocks x 1024 threads; warp w of block b computes j = b*32 + w.
__global__ void k_bw(const float* __restrict__ bwW, const float* __restrict__ bwB,
                     const float* __restrict__ encB) {
    __shared__ float enc[NB];
    int tid = threadIdx.x;
    if (tid < NB) {
        float e = encB[tid];
        #pragma unroll
        for (int c2 = 0; c2 < 4; c2++) e += g_encPart[c2 * NB + tid];
        enc[tid] = e;
        if (blockIdx.x == 0) g_encoded[tid] = e;
    }
    if (blockIdx.x == 0 && tid < NB * KK) g_S[tid] = 0.f;
    __syncthreads();
    int w = tid >> 5, lane = tid & 31;
    int j = blockIdx.x * 32 + w;                      // j in [0, 512)
    float z = bwW[j * NB + lane] * enc[lane];
    #pragma unroll
    for (int o = 16; o; o >>= 1) z += __shfl_xor_sync(0xffffffffu, z, o);
    if (lane == 0) {
        z += bwB[j];
        float s = 1.f / (1.f + expf(-z));
        float t = s * (100.0f / 60.0f);               // w*MU
        int i = j >> 4, c = j & 15;
        g_a[c * NB + i] = 1.f / (t * t);
    }
}

// ---- S[i][kk] = sum_p relu(1 - d^2 * a[i, label[p]]) ----
__global__ void k_sumS(const float* __restrict__ nd, const int* __restrict__ lab) {
    __shared__ __align__(16) float sa[MM * NB];
    __shared__ float bS[NB * KK];
    for (int t = threadIdx.x; t < MM * NB; t += blockDim.x) sa[t] = g_a[t];
    for (int t = threadIdx.x; t < NB * KK; t += blockDim.x) bS[t] = 0.f;
    __syncthreads();

    int lane = threadIdx.x & 31;                 // lane == kk
    int warp = (blockIdx.x * blockDim.x + threadIdx.x) >> 5;
    int nwarp = (gridDim.x * blockDim.x) >> 5;

    float acc[NB];
    #pragma unroll
    for (int i = 0; i < NB; i++) acc[i] = 0.f;

    for (int p = warp; p < NN; p += nwarp) {
        float d = nd[p * KK + lane];
        int c = lab[p];
        float md2 = -d * d;
        const float4* ac4 = (const float4*)&sa[c * NB];
        #pragma unroll
        for (int i8 = 0; i8 < 8; i8++) {
            float4 a4 = ac4[i8];
            acc[i8 * 4 + 0] += fmaxf(fmaf(md2, a4.x, 1.f), 0.f);
            acc[i8 * 4 + 1] += fmaxf(fmaf(md2, a4.y, 1.f), 0.f);
            acc[i8 * 4 + 2] += fmaxf(fmaf(md2, a4.z, 1.f), 0.f);
            acc[i8 * 4 + 3] += fmaxf(fmaf(md2, a4.w, 1.f), 0.f);
        }
    }
    #pragma unroll
    for (int i = 0; i < NB; i++)
        atomicAdd(&bS[i * KK + lane], acc[i]);
    __syncthreads();
    for (int t = threadIdx.x; t < NB * KK; t += blockDim.x)
        atomicAdd(&g_S[t], bS[t]);
}

// ---- out[p] = sum_kk sum_i E[i,kk]*relu(1-d^2*a[i,c])*decTh[nid][i] ----
// warp per p; lane = kk for coalesced d/nid loads; per round 8 kk x 4 lanes,
// each lane covers 8 i via one 16B LDG of fp16 decTh row.
__global__ void k_out(const float* __restrict__ nd, const int* __restrict__ nid,
                      const int* __restrict__ lab, float* __restrict__ out) {
    __shared__ __align__(16) float sa[MM * NB];
    __shared__ __align__(16) float sE[KK * NB];     // E[kk][i]
    for (int t = threadIdx.x; t < MM * NB; t += blockDim.x) sa[t] = g_a[t];
    for (int t = threadIdx.x; t < KK * NB; t += blockDim.x) {
        int i = t & 31, kk = t >> 5;
        sE[t] = g_encoded[i] / g_S[i * KK + kk];
    }
    __syncthreads();

    int lane = threadIdx.x & 31;
    int warp = (blockIdx.x * blockDim.x + threadIdx.x) >> 5;
    int nwarp = (gridDim.x * blockDim.x) >> 5;
    int r = lane & 3;        // i-chunk index (8 halves = 16B of the 64B row)
    int g = lane >> 2;       // kk subgroup within a round (8 per round)
    const float4* sa4 = (const float4*)sa;
    const float4* sE4 = (const float4*)sE;

    for (int p = warp; p < NN; p += nwarp) {
        float d_r = nd[p * KK + lane];
        int q_r = nid[p * KK + lane];
        int c = lab[p];
        float4 a0 = sa4[c * 8 + r * 2];
        float4 a1 = sa4[c * 8 + r * 2 + 1];
        float acc = 0.f;
        #pragma unroll
        for (int t = 0; t < 4; t++) {
            int kk = t * 8 + g;
            float d = __shfl_sync(0xffffffffu, d_r, kk);
            int q = __shfl_sync(0xffffffffu, q_r, kk);
            float md2 = -d * d;
            uint4 hv = *(const uint4*)&g_decTh[(size_t)q * NB + r * 8];
            float4 e0 = sE4[kk * 8 + r * 2];
            float4 e1 = sE4[kk * 8 + r * 2 + 1];
            float2 f0 = __half22float2(*(__half2*)&hv.x);
            float2 f1 = __half22float2(*(__half2*)&hv.y);
            float2 f2 = __half22float2(*(__half2*)&hv.z);
            float2 f3 = __half22float2(*(__half2*)&hv.w);
            float w0 = fmaxf(fmaf(md2, a0.x, 1.f), 0.f);
            float w1 = fmaxf(fmaf(md2, a0.y, 1.f), 0.f);
            float w2 = fmaxf(fmaf(md2, a0.z, 1.f), 0.f);
            float w3 = fmaxf(fmaf(md2, a0.w, 1.f), 0.f);
            float w4 = fmaxf(fmaf(md2, a1.x, 1.f), 0.f);
            float w5 = fmaxf(fmaf(md2, a1.y, 1.f), 0.f);
            float w6 = fmaxf(fmaf(md2, a1.z, 1.f), 0.f);
            float w7 = fmaxf(fmaf(md2, a1.w, 1.f), 0.f);
            acc = fmaf(w0 * e0.x, f0.x, acc);
            acc = fmaf(w1 * e0.y, f0.y, acc);
            acc = fmaf(w2 * e0.z, f1.x, acc);
            acc = fmaf(w3 * e0.w, f1.y, acc);
            acc = fmaf(w4 * e1.x, f2.x, acc);
            acc = fmaf(w5 * e1.y, f2.y, acc);
            acc = fmaf(w6 * e1.z, f3.x, acc);
            acc = fmaf(w7 * e1.w, f3.y, acc);
        }
        #pragma unroll
        for (int o = 16; o; o >>= 1) acc += __shfl_xor_sync(0xffffffffu, acc, o);
        if (lane == 0) out[p] = acc;
    }
}

extern "C" void kernel_launch(void* const* d_in, const int* in_sizes, int n_in,
                              void* d_out, int out_size) {
    const float* x    = (const float*)d_in[0];
    const float* encW = (const float*)d_in[1];
    const float* encB = (const float*)d_in[2];
    const float* dec  = (const float*)d_in[3];
    const float* bwW  = (const float*)d_in[4];
    const float* bwB  = (const float*)d_in[5];
    const float* nd   = (const float*)d_in[6];
    const int*   nidp = (const int*)d_in[7];
    const int*   lab  = (const int*)d_in[8];
    float* out = (float*)d_out;

    k_transpose<<<NN / 32, dim3(32, 8)>>>(dec);
    k_encode<<<dim3(4, NB), 256>>>(x, encW);
    k_bw<<<16, 1024>>>(bwW, bwB, encB);
    k_sumS<<<296, 256>>>(nd, lab);
    k_out<<<592, 256>>>(nd, nidp, lab, out);
}

// round 3
// speedup vs baseline: 1.1025x; 1.0476x over previous
#include <cuda_runtime.h>
#include <cuda_fp16.h>

#define NN 100000
#define NB 32      // n (bases)
#define MM 16      // m (clusters)
#define KK 32      // k (neighbours)

// ---- device scratch (no allocations allowed) ----
__device__ float g_encPart[4 * NB];     // encoder partial sums [chunk][i]
__device__ float g_encoded[NB];
__device__ float g_S[NB * KK];          // S[i][kk]
__device__ __align__(16) float g_a[MM * NB];          // a[c][i] = 1/(w*MU)^2
__device__ __align__(128) __half g_decTh[(size_t)NN * NB];  // decoder^T fp16 [N][32]

// ---- k1: fused transpose (blocks 0..3124) + encode partials (3125..3252) ----
__global__ void k_prep(const float* __restrict__ dec, const float* __restrict__ x,
                       const float* __restrict__ W) {
    if (blockIdx.x < NN / 32) {
        // transpose+convert decoder [32, N] -> decTh [N, 32] fp16
        __shared__ float tile[32][33];
        int p0 = blockIdx.x * 32;
        int tx = threadIdx.x & 31, ty = threadIdx.x >> 5;   // (32, 8)
        #pragma unroll
        for (int r = 0; r < 4; r++) {
            int i = ty + 8 * r;
            tile[i][tx] = dec[(size_t)i * NN + p0 + tx];
        }
        __syncthreads();
        #pragma unroll
        for (int r = 0; r < 4; r++) {
            int row = ty + 8 * r;
            g_decTh[(size_t)(p0 + row) * NB + tx] = __float2half(tile[tx][row]);
        }
    } else {
        // encoder partials: g_encPart[ck][i] = sum over chunk ck of x[p]*W[i,p]
        int e = blockIdx.x - NN / 32;
        int ck = e >> 5, i = e & 31;
        const float* Wr = W + (size_t)i * NN;
        int p0 = ck * (NN / 4);
        float acc = 0.f;
        for (int p = p0 + threadIdx.x; p < p0 + NN / 4; p += 256)
            acc = fmaf(x[p], Wr[p], acc);
        #pragma unroll
        for (int o = 16; o; o >>= 1) acc += __shfl_xor_sync(0xffffffffu, acc, o);
        __shared__ float s[8];
        if ((threadIdx.x & 31) == 0) s[threadIdx.x >> 5] = acc;
        __syncthreads();
        if (threadIdx.x == 0) {
            float t = 0.f;
            #pragma unroll
            for (int j = 0; j < 8; j++) t += s[j];
            g_encPart[ck * NB + i] = t;
        }
    }
}

// ---- k2: finalize encoded, zero S, warp-per-j bw linear -> g_a ----
__global__ void k_bw(const float* __restrict__ bwW, const float* __restrict__ bwB,
                     const float* __restrict__ encB) {
    __shared__ float enc[NB];
    int tid = threadIdx.x;
    if (tid < NB) {
        float e = encB[tid];
        #pragma unroll
        for (int c2 = 0; c2 < 4; c2++) e += g_encPart[c2 * NB + tid];
        enc[tid] = e;
        if (blockIdx.x == 0) g_encoded[tid] = e;
    }
    if (blockIdx.x == 0 && tid < NB * KK) g_S[tid] = 0.f;
    __syncthreads();
    int w = tid >> 5, lane = tid & 31;
    int j = blockIdx.x * 32 + w;                      // j in [0, 512)
    float z = bwW[j * NB + lane] * enc[lane];
    #pragma unroll
    for (int o = 16; o; o >>= 1) z += __shfl_xor_sync(0xffffffffu, z, o);
    if (lane == 0) {
        z += bwB[j];
        float s = 1.f / (1.f + expf(-z));
        float t = s * (100.0f / 60.0f);               // w*MU
        int i = j >> 4, c = j & 15;
        g_a[c * NB + i] = 1.f / (t * t);
    }
}

// ---- k3: S[i][kk] = sum_p relu(1 - d^2 * a[i, label[p]]) ----
// warp handles 16 i-values (half h) for a stream of points; lane = kk.
// Software-pipelined point prefetch; 6 blocks/SM for 75% occupancy.
__global__ void __launch_bounds__(256, 6)
k_sumS(const float* __restrict__ nd, const int* __restrict__ lab) {
    __shared__ __align__(16) float sa[MM * NB];
    __shared__ float bS[NB * KK];
    for (int t = threadIdx.x; t < MM * NB; t += 256) sa[t] = g_a[t];
    for (int t = threadIdx.x; t < NB * KK; t += 256) bS[t] = 0.f;
    __syncthreads();

    int lane = threadIdx.x & 31;                    // lane == kk
    int gw = (blockIdx.x * 256 + threadIdx.x) >> 5; // global warp id
    int h = gw & 1;                                 // which i-half
    int stream = gw >> 1;
    const int nstream = (gridDim.x * 8) >> 1;

    float acc[16];
    #pragma unroll
    for (int ii = 0; ii < 16; ii++) acc[ii] = 0.f;

    int p = stream;
    if (p < NN) {
        float d = nd[p * KK + lane];
        int c = lab[p];
        while (true) {
            int pn = p + nstream;
            float dn = 0.f; int cn = 0;
            if (pn < NN) { dn = nd[pn * KK + lane]; cn = lab[pn]; }
            float md2 = -d * d;
            const float4* a4 = (const float4*)&sa[c * NB + h * 16];
            #pragma unroll
            for (int q = 0; q < 4; q++) {
                float4 av = a4[q];
                acc[q * 4 + 0] += fmaxf(fmaf(md2, av.x, 1.f), 0.f);
                acc[q * 4 + 1] += fmaxf(fmaf(md2, av.y, 1.f), 0.f);
                acc[q * 4 + 2] += fmaxf(fmaf(md2, av.z, 1.f), 0.f);
                acc[q * 4 + 3] += fmaxf(fmaf(md2, av.w, 1.f), 0.f);
            }
            if (pn >= NN) break;
            p = pn; d = dn; c = cn;
        }
    }
    #pragma unroll
    for (int ii = 0; ii < 16; ii++)
        atomicAdd(&bS[(h * 16 + ii) * KK + lane], acc[ii]);
    __syncthreads();
    for (int t = threadIdx.x; t < NB * KK; t += 256)
        atomicAdd(&g_S[t], bS[t]);
}

// ---- k4: out[p] = sum_kk sum_i E[i,kk]*relu(1-d^2*a[i,c])*decTh[nid][i] ----
// warp per p; lane = kk for coalesced d/nid loads; per round 8 kk x 4 lanes,
// each lane covers 8 i via one 16B LDG of the fp16 decTh row.
__global__ void k_out(const float* __restrict__ nd, const int* __restrict__ nid,
                      const int* __restrict__ lab, float* __restrict__ out) {
    __shared__ __align__(16) float sa[MM * NB];
    __shared__ __align__(16) float sE[KK * NB];     // E[kk][i]
    for (int t = threadIdx.x; t < MM * NB; t += blockDim.x) sa[t] = g_a[t];
    for (int t = threadIdx.x; t < KK * NB; t += blockDim.x) {
        int i = t & 31, kk = t >> 5;
        sE[t] = g_encoded[i] / g_S[i * KK + kk];
    }
    __syncthreads();

    int lane = threadIdx.x & 31;
    int warp = (blockIdx.x * blockDim.x + threadIdx.x) >> 5;
    int nwarp = (gridDim.x * blockDim.x) >> 5;
    int r = lane & 3;        // i-chunk (8 halves = 16B of the 64B row)
    int g = lane >> 2;       // kk subgroup within a round (8 per round)
    const float4* sa4 = (const float4*)sa;
    const float4* sE4 = (const float4*)sE;

    for (int p = warp; p < NN; p += nwarp) {
        float d_r = nd[p * KK + lane];
        int q_r = nid[p * KK + lane];
        int c = lab[p];
        float4 a0 = sa4[c * 8 + r * 2];
        float4 a1 = sa4[c * 8 + r * 2 + 1];
        float acc = 0.f;
        #pragma unroll
        for (int t = 0; t < 4; t++) {
            int kk = t * 8 + g;
            float d = __shfl_sync(0xffffffffu, d_r, kk);
            int q = __shfl_sync(0xffffffffu, q_r, kk);
            float md2 = -d * d;
            uint4 hv = *(const uint4*)&g_decTh[(size_t)q * NB + r * 8];
            float4 e0 = sE4[kk * 8 + r * 2];
            float4 e1 = sE4[kk * 8 + r * 2 + 1];
            float2 f0 = __half22float2(*(__half2*)&hv.x);
            float2 f1 = __half22float2(*(__half2*)&hv.y);
            float2 f2 = __half22float2(*(__half2*)&hv.z);
            float2 f3 = __half22float2(*(__half2*)&hv.w);
            float w0 = fmaxf(fmaf(md2, a0.x, 1.f), 0.f);
            float w1 = fmaxf(fmaf(md2, a0.y, 1.f), 0.f);
            float w2 = fmaxf(fmaf(md2, a0.z, 1.f), 0.f);
            float w3 = fmaxf(fmaf(md2, a0.w, 1.f), 0.f);
            float w4 = fmaxf(fmaf(md2, a1.x, 1.f), 0.f);
            float w5 = fmaxf(fmaf(md2, a1.y, 1.f), 0.f);
            float w6 = fmaxf(fmaf(md2, a1.z, 1.f), 0.f);
            float w7 = fmaxf(fmaf(md2, a1.w, 1.f), 0.f);
            acc = fmaf(w0 * e0.x, f0.x, acc);
            acc = fmaf(w1 * e0.y, f0.y, acc);
            acc = fmaf(w2 * e0.z, f1.x, acc);
            acc = fmaf(w3 * e0.w, f1.y, acc);
            acc = fmaf(w4 * e1.x, f2.x, acc);
            acc = fmaf(w5 * e1.y, f2.y, acc);
            acc = fmaf(w6 * e1.z, f3.x, acc);
            acc = fmaf(w7 * e1.w, f3.y, acc);
        }
        #pragma unroll
        for (int o = 16; o; o >>= 1) acc += __shfl_xor_sync(0xffffffffu, acc, o);
        if (lane == 0) out[p] = acc;
    }
}

extern "C" void kernel_launch(void* const* d_in, const int* in_sizes, int n_in,
                              void* d_out, int out_size) {
    const float* x    = (const float*)d_in[0];
    const float* encW = (const float*)d_in[1];
    const float* encB = (const float*)d_in[2];
    const float* dec  = (const float*)d_in[3];
    const float* bwW  = (const float*)d_in[4];
    const float* bwB  = (const float*)d_in[5];
    const float* nd   = (const float*)d_in[6];
    const int*   nidp = (const int*)d_in[7];
    const int*   lab  = (const int*)d_in[8];
    float* out = (float*)d_out;

    k_prep<<<NN / 32 + 128, 256>>>(dec, x, encW);
    k_bw<<<16, 1024>>>(bwW, bwB, encB);
    k_sumS<<<888, 256>>>(nd, lab);
    k_out<<<592, 256>>>(nd, nidp, lab, out);
}

// round 4
// speedup vs baseline: 1.2086x; 1.0963x over previous
#include <cuda_runtime.h>
#include <cuda_fp16.h>

#define NN 100000
#define NB 32      // n (bases)
#define MM 16      // m (clusters)
#define KK 32      // k (neighbours)

// ---- device scratch (no allocations allowed) ----
__device__ float g_encPart[4 * NB];     // encoder partial sums [chunk][i]
__device__ float g_encoded[NB];
__device__ float g_S[NB * KK];          // S[i][kk]
__device__ __align__(16) float g_a[MM * NB];          // a[c][i] = 1/(w*MU)^2
__device__ __align__(128) __half g_decTh[(size_t)NN * NB];  // decoder^T fp16 [N][32]

// ---- k1: fused transpose (blocks 0..3124) + encode partials (3125..3252) ----
__global__ void k_prep(const float* __restrict__ dec, const float* __restrict__ x,
                       const float* __restrict__ W) {
    if (blockIdx.x < NN / 32) {
        __shared__ float tile[32][33];
        int p0 = blockIdx.x * 32;
        int tx = threadIdx.x & 31, ty = threadIdx.x >> 5;   // (32, 8)
        #pragma unroll
        for (int r = 0; r < 4; r++) {
            int i = ty + 8 * r;
            tile[i][tx] = dec[(size_t)i * NN + p0 + tx];
        }
        __syncthreads();
        #pragma unroll
        for (int r = 0; r < 4; r++) {
            int row = ty + 8 * r;
            g_decTh[(size_t)(p0 + row) * NB + tx] = __float2half(tile[tx][row]);
        }
    } else {
        int e = blockIdx.x - NN / 32;
        int ck = e >> 5, i = e & 31;
        const float* Wr = W + (size_t)i * NN;
        int p0 = ck * (NN / 4);
        float acc = 0.f;
        for (int p = p0 + threadIdx.x; p < p0 + NN / 4; p += 256)
            acc = fmaf(x[p], Wr[p], acc);
        #pragma unroll
        for (int o = 16; o; o >>= 1) acc += __shfl_xor_sync(0xffffffffu, acc, o);
        __shared__ float s[8];
        if ((threadIdx.x & 31) == 0) s[threadIdx.x >> 5] = acc;
        __syncthreads();
        if (threadIdx.x == 0) {
            float t = 0.f;
            #pragma unroll
            for (int j = 0; j < 8; j++) t += s[j];
            g_encPart[ck * NB + i] = t;
        }
    }
}

// ---- k2: finalize encoded, zero S, warp-per-j bw linear -> g_a ----
__global__ void k_bw(const float* __restrict__ bwW, const float* __restrict__ bwB,
                     const float* __restrict__ encB) {
    __shared__ float enc[NB];
    int tid = threadIdx.x;
    if (tid < NB) {
        float e = encB[tid];
        #pragma unroll
        for (int c2 = 0; c2 < 4; c2++) e += g_encPart[c2 * NB + tid];
        enc[tid] = e;
        if (blockIdx.x == 0) g_encoded[tid] = e;
    }
    if (blockIdx.x == 0 && tid < NB * KK) g_S[tid] = 0.f;
    __syncthreads();
    int w = tid >> 5, lane = tid & 31;
    int j = blockIdx.x * 32 + w;                      // j in [0, 512)
    float z = bwW[j * NB + lane] * enc[lane];
    #pragma unroll
    for (int o = 16; o; o >>= 1) z += __shfl_xor_sync(0xffffffffu, z, o);
    if (lane == 0) {
        z += bwB[j];
        float s = 1.f / (1.f + expf(-z));
        float t = s * (100.0f / 60.0f);               // w*MU
        int i = j >> 4, c = j & 15;
        g_a[c * NB + i] = 1.f / (t * t);
    }
}

// ---- k3: S[i][kk] = sum_p relu(1 - d^2 * a[i, label[p]]) ----
__global__ void __launch_bounds__(256, 6)
k_sumS(const float* __restrict__ nd, const int* __restrict__ lab) {
    __shared__ __align__(16) float sa[MM * NB];
    __shared__ float bS[NB * KK];
    for (int t = threadIdx.x; t < MM * NB; t += 256) sa[t] = g_a[t];
    for (int t = threadIdx.x; t < NB * KK; t += 256) bS[t] = 0.f;
    __syncthreads();

    int lane = threadIdx.x & 31;                    // lane == kk
    int gw = (blockIdx.x * 256 + threadIdx.x) >> 5;
    int h = gw & 1;                                 // which i-half
    int stream = gw >> 1;
    const int nstream = (gridDim.x * 8) >> 1;

    float acc[16];
    #pragma unroll
    for (int ii = 0; ii < 16; ii++) acc[ii] = 0.f;

    int p = stream;
    if (p < NN) {
        float d = nd[p * KK + lane];
        int c = lab[p];
        while (true) {
            int pn = p + nstream;
            float dn = 0.f; int cn = 0;
            if (pn < NN) { dn = nd[pn * KK + lane]; cn = lab[pn]; }
            float md2 = -d * d;
            const float4* a4 = (const float4*)&sa[c * NB + h * 16];
            #pragma unroll
            for (int q = 0; q < 4; q++) {
                float4 av = a4[q];
                acc[q * 4 + 0] += fmaxf(fmaf(md2, av.x, 1.f), 0.f);
                acc[q * 4 + 1] += fmaxf(fmaf(md2, av.y, 1.f), 0.f);
                acc[q * 4 + 2] += fmaxf(fmaf(md2, av.z, 1.f), 0.f);
                acc[q * 4 + 3] += fmaxf(fmaf(md2, av.w, 1.f), 0.f);
            }
            if (pn >= NN) break;
            p = pn; d = dn; c = cn;
        }
    }
    #pragma unroll
    for (int ii = 0; ii < 16; ii++)
        atomicAdd(&bS[(h * 16 + ii) * KK + lane], acc[ii]);
    __syncthreads();
    for (int t = threadIdx.x; t < NB * KK; t += 256)
        atomicAdd(&g_S[t], bS[t]);
}

// ---- k4: out[p] = sum_kk sum_i E[i,kk]*relu(1-d^2*a[i,c])*decTh[nid][i] ----
// warp per p; lane = kk for coalesced d/nid loads; per round 8 kk x 4 lanes,
// each lane covers 8 i via one 16B LDG of the fp16 decTh row.
// E values (p-invariant) live in registers; point + gather software pipeline.
__global__ void __launch_bounds__(256, 4)
k_out(const float* __restrict__ nd, const int* __restrict__ nid,
      const int* __restrict__ lab, float* __restrict__ out) {
    __shared__ __align__(16) float sa[MM * NB];
    __shared__ __align__(16) float sE[KK * NB];     // E[kk][i]
    for (int t = threadIdx.x; t < MM * NB; t += blockDim.x) sa[t] = g_a[t];
    for (int t = threadIdx.x; t < KK * NB; t += blockDim.x) {
        int i = t & 31, kk = t >> 5;
        sE[t] = g_encoded[i] / g_S[i * KK + kk];
    }
    __syncthreads();

    int lane = threadIdx.x & 31;
    int warp = (blockIdx.x * blockDim.x + threadIdx.x) >> 5;
    int nwarp = (gridDim.x * blockDim.x) >> 5;
    int r = lane & 3;        // i-chunk (8 halves = 16B of the 64B row)
    int g = lane >> 2;       // kk subgroup within a round (8 per round)
    const float4* sa4 = (const float4*)sa;
    const float4* sE4 = (const float4*)sE;

    // hoist E into registers: this lane's 32 needed values
    float4 E0[4], E1[4];
    #pragma unroll
    for (int t = 0; t < 4; t++) {
        int kk = t * 8 + g;
        E0[t] = sE4[kk * 8 + r * 2];
        E1[t] = sE4[kk * 8 + r * 2 + 1];
    }

    int p = warp;
    if (p >= NN) return;
    float d_r = nd[p * KK + lane];
    int   q_r = nid[p * KK + lane];
    int   c   = lab[p];

    while (true) {
        // prefetch next point's row data
        int pn = p + nwarp;
        float dn = 0.f; int qn = 0, cn = 0;
        if (pn < NN) {
            dn = nd[pn * KK + lane];
            qn = nid[pn * KK + lane];
            cn = lab[pn];
        }

        float4 a0 = sa4[c * 8 + r * 2];
        float4 a1 = sa4[c * 8 + r * 2 + 1];
        float acc = 0.f;

        // 2-stage gather pipeline over the 4 rounds
        float d0 = __shfl_sync(0xffffffffu, d_r, g);
        int   q0 = __shfl_sync(0xffffffffu, q_r, g);
        uint4 hv = *(const uint4*)&g_decTh[(size_t)q0 * NB + r * 8];
        float dcur = d0;
        #pragma unroll
        for (int t = 0; t < 4; t++) {
            uint4 hvn; float dnx = 0.f;
            if (t < 3) {
                int kk = (t + 1) * 8 + g;
                dnx = __shfl_sync(0xffffffffu, d_r, kk);
                int q = __shfl_sync(0xffffffffu, q_r, kk);
                hvn = *(const uint4*)&g_decTh[(size_t)q * NB + r * 8];
            }
            float md2 = -dcur * dcur;
            float2 f0 = __half22float2(*(__half2*)&hv.x);
            float2 f1 = __half22float2(*(__half2*)&hv.y);
            float2 f2 = __half22float2(*(__half2*)&hv.z);
            float2 f3 = __half22float2(*(__half2*)&hv.w);
            float w0 = fmaxf(fmaf(md2, a0.x, 1.f), 0.f);
            float w1 = fmaxf(fmaf(md2, a0.y, 1.f), 0.f);
            float w2 = fmaxf(fmaf(md2, a0.z, 1.f), 0.f);
            float w3 = fmaxf(fmaf(md2, a0.w, 1.f), 0.f);
            float w4 = fmaxf(fmaf(md2, a1.x, 1.f), 0.f);
            float w5 = fmaxf(fmaf(md2, a1.y, 1.f), 0.f);
            float w6 = fmaxf(fmaf(md2, a1.z, 1.f), 0.f);
            float w7 = fmaxf(fmaf(md2, a1.w, 1.f), 0.f);
            acc = fmaf(w0 * E0[t].x, f0.x, acc);
            acc = fmaf(w1 * E0[t].y, f0.y, acc);
            acc = fmaf(w2 * E0[t].z, f1.x, acc);
            acc = fmaf(w3 * E0[t].w, f1.y, acc);
            acc = fmaf(w4 * E1[t].x, f2.x, acc);
            acc = fmaf(w5 * E1[t].y, f2.y, acc);
            acc = fmaf(w6 * E1[t].z, f3.x, acc);
            acc = fmaf(w7 * E1[t].w, f3.y, acc);
            hv = hvn; dcur = dnx;
        }
        #pragma unroll
        for (int o = 16; o; o >>= 1) acc += __shfl_xor_sync(0xffffffffu, acc, o);
        if (lane == 0) out[p] = acc;

        if (pn >= NN) break;
        p = pn; d_r = dn; q_r = qn; c = cn;
    }
}

extern "C" void kernel_launch(void* const* d_in, const int* in_sizes, int n_in,
                              void* d_out, int out_size) {
    const float* x    = (const float*)d_in[0];
    const float* encW = (const float*)d_in[1];
    const float* encB = (const float*)d_in[2];
    const float* dec  = (const float*)d_in[3];
    const float* bwW  = (const float*)d_in[4];
    const float* bwB  = (const float*)d_in[5];
    const float* nd   = (const float*)d_in[6];
    const int*   nidp = (const int*)d_in[7];
    const int*   lab  = (const int*)d_in[8];
    float* out = (float*)d_out;

    k_prep<<<NN / 32 + 128, 256>>>(dec, x, encW);
    k_bw<<<16, 1024>>>(bwW, bwB, encB);
    k_sumS<<<888, 256>>>(nd, lab);
    k_out<<<592, 256>>>(nd, nidp, lab, out);
}